// round 11
// baseline (speedup 1.0000x reference)
#include <cuda_runtime.h>
#include <cstdint>
#include <math.h>

#define SEQ 2048
#define MR  4096

// ---------------- scratch (device globals; no allocs) ----------------
__device__ float g_xr [MR*1024];            // x rounded to tf32
__device__ float g_wr [3*1024*1024];        // qkv_w rounded
__device__ float g_pwr[1024*1024];          // proj_w rounded
__device__ float g_qkv[(size_t)MR*3072];    // q(*0.125)|k|v rounded, row-major [s][3072]
__device__ float g_ctx[(size_t)MR*1024];    // attention out rounded

// ---------------- helpers ----------------
__device__ __forceinline__ uint32_t sm_u32(const void* p){
    uint32_t a;
    asm("{ .reg .u64 t; cvta.to.shared.u64 t, %1; cvt.u32.u64 %0, t; }" : "=r"(a) : "l"(p));
    return a;
}
__device__ __forceinline__ float rnaf(float x){
    uint32_t u; asm("cvt.rna.tf32.f32 %0, %1;" : "=r"(u) : "f"(x)); return __uint_as_float(u);
}
#define CP16(dst,src) asm volatile("cp.async.cg.shared.global [%0], [%1], 16;" :: "r"(dst),"l"(src))
#define CPC()  asm volatile("cp.async.commit_group;")
#define CPW(n) asm volatile("cp.async.wait_group %0;" :: "n"(n))

__device__ __forceinline__ void mma8(float* c, const uint32_t* a, const uint32_t* b){
    asm volatile("mma.sync.aligned.m16n8k8.row.col.f32.tf32.tf32.f32 "
        "{%0,%1,%2,%3}, {%4,%5,%6,%7}, {%8,%9}, {%0,%1,%2,%3};"
        : "+f"(c[0]),"+f"(c[1]),"+f"(c[2]),"+f"(c[3])
        : "r"(a[0]),"r"(a[1]),"r"(a[2]),"r"(a[3]), "r"(b[0]),"r"(b[1]));
}
__device__ __forceinline__ void ldsm4(uint32_t* r, uint32_t a){
    asm volatile("ldmatrix.sync.aligned.m8n8.x4.shared.b16 {%0,%1,%2,%3}, [%4];"
        : "=r"(r[0]),"=r"(r[1]),"=r"(r[2]),"=r"(r[3]) : "r"(a));
}

// ---------------------------------------------------------------------------
// fp32 -> tf32 (rna) pre-round. which: 0->g_xr, 1->g_wr, 2->g_pwr
// ---------------------------------------------------------------------------
__global__ void round_k(const float4* __restrict__ in, int which, int n4)
{
    int i = blockIdx.x * blockDim.x + threadIdx.x;
    if (i >= n4) return;
    float4* out = (which==0) ? (float4*)g_xr : (which==1) ? (float4*)g_wr : (float4*)g_pwr;
    float4 v = in[i];
    v.x = rnaf(v.x); v.y = rnaf(v.y); v.z = rnaf(v.z); v.w = rnaf(v.w);
    out[i] = v;
}

// ---------------------------------------------------------------------------
// tf32 mma.sync GEMM: C[M,N] = A[M,1024] @ B[N,1024]^T + bias
// CTA 128x128, warp tile 32x64 (4x2 warps), BK=16, 3-stage cp.async, ldmatrix.
// 256 thr, 2 CTAs/SM (<=128 regs).
// MODE 1: A=g_xr, B=g_wr, N=3072 -> g_qkv (rounded; q cols scaled 0.125)
// MODE 2: A=g_ctx, B=g_pwr, N=1024 -> C (plain fp32)
// dyn smem: A 3*8192 | B 3*8192 = 49152 B
// ---------------------------------------------------------------------------
template<int MODE>
__global__ __launch_bounds__(256, 2)
void mm_mma(const float* __restrict__ bias, float* __restrict__ C)
{
    extern __shared__ char smem[];
    const int N = (MODE==1) ? 3072 : 1024;
    uint32_t ab = sm_u32(smem);
    uint32_t bb = ab + 24576;
    const float* Ap = (MODE==1) ? g_xr : g_ctx;
    const float* Bp = (MODE==1) ? g_wr : g_pwr;
    float* Cp = (MODE==1) ? g_qkv : C;

    int tid = threadIdx.x, wid = tid>>5, lane = tid&31;
    int g = lane>>2, tg = lane&3;
    int wm = wid&3, wn = wid>>2;
    int bm = blockIdx.y*128, bn = blockIdx.x*128;

    auto aaddr = [&](int st,int r,int c){ return ab + st*8192 + r*64 + ((c ^ ((r>>1)&3))<<4); };
    auto baddr = [&](int st,int r,int c){ return bb + st*8192 + r*64 + ((c ^ ((r>>1)&3))<<4); };

    auto pf = [&](int kt, int st){
#pragma unroll
        for (int j=0;j<2;j++){
            int ci = j*256 + tid, r = ci>>2, c = ci&3;
            CP16(aaddr(st,r,c), Ap + (size_t)(bm+r)*1024 + kt*16 + c*4);
        }
#pragma unroll
        for (int j=0;j<2;j++){
            int ci = j*256 + tid, r = ci>>2, c = ci&3;
            CP16(baddr(st,r,c), Bp + (size_t)(bn+r)*1024 + kt*16 + c*4);
        }
    };

    float acc[2][8][4];
#pragma unroll
    for (int mt=0;mt<2;mt++)
#pragma unroll
        for (int nt=0;nt<8;nt++)
#pragma unroll
            for (int q=0;q<4;q++) acc[mt][nt][q] = 0.f;

    pf(0,0); CPC();
    pf(1,1); CPC();
    for (int kt=0; kt<64; kt++){
        int st = kt % 3;
        CPW(1);
        __syncthreads();
        if (kt+2 < 64) pf(kt+2, (kt+2)%3);
        CPC();
#pragma unroll
        for (int k8=0;k8<2;k8++){
            uint32_t a[2][4], b2[8][2];
#pragma unroll
            for (int mt=0;mt<2;mt++){
                int r = wm*32 + mt*16 + (lane&15);
                int c = k8*2 + ((lane>>4)&1);
                ldsm4(a[mt], aaddr(st,r,c));
            }
#pragma unroll
            for (int np=0;np<4;np++){
                int r = wn*64 + np*16 + (lane&7) + ((lane>>4)&1)*8;
                int c = k8*2 + ((lane>>3)&1);
                uint32_t t4[4];
                ldsm4(t4, baddr(st,r,c));
                b2[2*np][0]=t4[0];   b2[2*np][1]=t4[1];
                b2[2*np+1][0]=t4[2]; b2[2*np+1][1]=t4[3];
            }
#pragma unroll
            for (int mt=0;mt<2;mt++)
#pragma unroll
                for (int nt=0;nt<8;nt++)
                    mma8(acc[mt][nt], a[mt], b2[nt]);
        }
    }

#pragma unroll
    for (int mt=0;mt<2;mt++){
        int r0 = bm + wm*32 + mt*16 + g;
#pragma unroll
        for (int nt=0;nt<8;nt++){
            int c0 = bn + wn*64 + nt*8 + 2*tg;
            float b0 = bias[c0], b1 = bias[c0+1];
            float v0 = acc[mt][nt][0]+b0, v1 = acc[mt][nt][1]+b1;
            float v2 = acc[mt][nt][2]+b0, v3 = acc[mt][nt][3]+b1;
            if (MODE==1){
                float sc = (c0 < 1024) ? 0.125f : 1.f;
                v0=rnaf(v0*sc); v1=rnaf(v1*sc); v2=rnaf(v2*sc); v3=rnaf(v3*sc);
            }
            *(float2*)&Cp[(size_t)r0*N + c0]     = make_float2(v0,v1);
            *(float2*)&Cp[(size_t)(r0+8)*N + c0] = make_float2(v2,v3);
        }
    }
}

// ---------------------------------------------------------------------------
// Flash attention, mma.sync tf32. CTA = 256 queries of one (b,h), 512 thr,
// 16 warps x 16 rows. Bc=64 keys/iter, 32 iters. ldmatrix Q/K/P fragments.
// dyn smem: Q[256x64f swz] 65536 | K 2x16384 | V 2x(64x272B) | P 65536 = 198656
// ---------------------------------------------------------------------------
__global__ __launch_bounds__(512, 1)
void attn_mma()
{
    extern __shared__ char smem[];
    uint32_t sb = sm_u32(smem);
    const uint32_t QO = 0, KO = 65536, VO = 98304, PO = 133120;

    int tid = threadIdx.x, wid = tid>>5, lane = tid&31;
    int g = lane>>2, tg = lane&3;
    int bh = blockIdx.y, b = bh>>4, hh = bh&15;
    int q0 = blockIdx.x * 256;

    const float* Qg  = g_qkv + (size_t)(b*2048 + q0)*3072 + hh*64;
    const float* KVg = g_qkv + (size_t)(b*2048)*3072 + 1024 + hh*64;

    auto qaddr = [&](int r,int c){ return sb + QO + r*256 + ((c ^ (r&7))<<4); };
    auto kaddr = [&](int st,int r,int c){ return sb + KO + st*16384 + r*256 + ((c ^ (r&7))<<4); };
    auto vaddr = [&](int st,int r,int c){ return sb + VO + st*17408 + r*272 + c*16; };
    auto paddr = [&](int r,int c){ return sb + PO + r*256 + ((c ^ (r&7))<<4); };

    // Q tile: 256 rows x 16 chunks = 4096 cp16, 8/thread
#pragma unroll
    for (int j=0;j<8;j++){
        int ci = j*512 + tid, r = ci>>4, c = ci&15;
        CP16(qaddr(r,c), Qg + (size_t)r*3072 + c*4);
    }
    auto pf = [&](int it, int st){
        int kt = it * 64;
#pragma unroll
        for (int j=0;j<2;j++){
            int ci = j*512 + tid, r = ci>>4, c = ci&15;
            CP16(kaddr(st,r,c), KVg + (size_t)(kt+r)*3072 + c*4);
        }
#pragma unroll
        for (int j=0;j<2;j++){
            int ci = j*512 + tid, r = ci>>4, c = ci&15;
            CP16(vaddr(st,r,c), KVg + (size_t)(kt+r)*3072 + 1024 + c*4);
        }
    };

    float o[8][4], m[2], l[2];
    m[0]=m[1]=-1e30f; l[0]=l[1]=0.f;
#pragma unroll
    for (int nt=0;nt<8;nt++)
#pragma unroll
        for (int q=0;q<4;q++) o[nt][q]=0.f;

    pf(0,0); CPC();
    for (int it=0; it<32; it++){
        int st = it & 1;
        if (it+1 < 32){ pf(it+1, st^1); CPC(); CPW(1); } else CPW(0);
        __syncthreads();

        // ---- S = Q @ K^T : warp rows wid*16..+15, cols 0..63 ----
        float s[8][4];
#pragma unroll
        for (int nt=0;nt<8;nt++)
#pragma unroll
            for (int q=0;q<4;q++) s[nt][q]=0.f;
#pragma unroll
        for (int k8=0;k8<8;k8++){
            uint32_t a[4], b2[8][2];
            {
                int r = wid*16 + (lane&15);
                int c = k8*2 + ((lane>>4)&1);
                ldsm4(a, qaddr(r,c));
            }
#pragma unroll
            for (int np=0;np<4;np++){
                int r = np*16 + (lane&7) + ((lane>>4)&1)*8;
                int c = k8*2 + ((lane>>3)&1);
                uint32_t t4[4];
                ldsm4(t4, kaddr(st,r,c));
                b2[2*np][0]=t4[0];   b2[2*np][1]=t4[1];
                b2[2*np+1][0]=t4[2]; b2[2*np+1][1]=t4[3];
            }
#pragma unroll
            for (int nt=0;nt<8;nt++) mma8(s[nt], a, b2[nt]);
        }

        // ---- online softmax: 2 row-states per thread ----
        float al[2];
#pragma unroll
        for (int hf=0;hf<2;hf++){
            float mx = -1e30f;
#pragma unroll
            for (int nt=0;nt<8;nt++)
                mx = fmaxf(mx, fmaxf(s[nt][2*hf], s[nt][2*hf+1]));
            mx = fmaxf(mx, __shfl_xor_sync(0xffffffffu, mx, 1));
            mx = fmaxf(mx, __shfl_xor_sync(0xffffffffu, mx, 2));
            float mn = fmaxf(m[hf], mx);
            al[hf] = __expf(m[hf] - mn);
            m[hf] = mn;
            float sum = 0.f;
#pragma unroll
            for (int nt=0;nt<8;nt++){
                s[nt][2*hf]   = __expf(s[nt][2*hf]   - mn); sum += s[nt][2*hf];
                s[nt][2*hf+1] = __expf(s[nt][2*hf+1] - mn); sum += s[nt][2*hf+1];
            }
            sum += __shfl_xor_sync(0xffffffffu, sum, 1);
            sum += __shfl_xor_sync(0xffffffffu, sum, 2);
            l[hf] = l[hf]*al[hf] + sum;
        }
#pragma unroll
        for (int nt=0;nt<8;nt++){
            o[nt][0]*=al[0]; o[nt][1]*=al[0];
            o[nt][2]*=al[1]; o[nt][3]*=al[1];
        }

        // ---- stage P (rounded) via GENERIC pointers, own-warp rows ----
        {
            int row = wid*16 + g;
            int coff = (2*tg & 3) * 4;
#pragma unroll
            for (int nt=0;nt<8;nt++){
                int ch = (nt*8 + 2*tg) >> 2;
                char* p0 = smem + PO + row*256     + (((ch ^ (row&7))<<4))     + coff;
                char* p1 = smem + PO + (row+8)*256 + (((ch ^ ((row+8)&7))<<4)) + coff;
                *(float2*)p0 = make_float2(rnaf(s[nt][0]), rnaf(s[nt][1]));
                *(float2*)p1 = make_float2(rnaf(s[nt][2]), rnaf(s[nt][3]));
            }
        }
        __syncwarp();

        // ---- O += P @ V ----
#pragma unroll
        for (int k8=0;k8<8;k8++){
            uint32_t a[4];
            {
                int r = wid*16 + (lane&15);
                int c = k8*2 + ((lane>>4)&1);
                ldsm4(a, paddr(r,c));
            }
            const float* v0 = (const float*)(smem + VO + st*17408 + (k8*8+tg  )*272);
            const float* v1 = (const float*)(smem + VO + st*17408 + (k8*8+tg+4)*272);
#pragma unroll
            for (int nt=0;nt<8;nt++){
                uint32_t b2[2] = { __float_as_uint(v0[nt*8+g]), __float_as_uint(v1[nt*8+g]) };
                mma8(o[nt], a, b2);
            }
        }
        __syncthreads();
    }

    // ---- epilogue: normalize, round, write ctx ----
    float i0 = 1.f/l[0], i1 = 1.f/l[1];
    int r0 = q0 + wid*16 + g;
    float* Cg = g_ctx + (size_t)(b*2048 + r0)*1024 + hh*64;
#pragma unroll
    for (int nt=0;nt<8;nt++){
        int c = nt*8 + 2*tg;
        *(float2*)&Cg[c]          = make_float2(rnaf(o[nt][0]*i0), rnaf(o[nt][1]*i0));
        *(float2*)&Cg[8*1024 + c] = make_float2(rnaf(o[nt][2]*i1), rnaf(o[nt][3]*i1));
    }
}

// ---------------------------------------------------------------------------
extern "C" void kernel_launch(void* const* d_in, const int* in_sizes, int n_in,
                              void* d_out, int out_size)
{
    const float* x      = (const float*)d_in[0];
    const float* qkv_w  = (const float*)d_in[1];
    const float* qkv_b  = (const float*)d_in[2];
    const float* proj_w = (const float*)d_in[3];
    const float* proj_b = (const float*)d_in[4];
    float* out = (float*)d_out;
    (void)in_sizes; (void)n_in; (void)out_size;

    const int GSM = 49152;    // GEMM: 3-stage A(8K)+B(8K)
    const int ASM = 198656;   // attention
    cudaFuncSetAttribute(mm_mma<1>, cudaFuncAttributeMaxDynamicSharedMemorySize, GSM);
    cudaFuncSetAttribute(mm_mma<2>, cudaFuncAttributeMaxDynamicSharedMemorySize, GSM);
    cudaFuncSetAttribute(attn_mma,  cudaFuncAttributeMaxDynamicSharedMemorySize, ASM);

    round_k<<<4096, 256>>>((const float4*)x,      0, 1048576);
    round_k<<<3072, 256>>>((const float4*)qkv_w,  1,  786432);
    round_k<<<1024, 256>>>((const float4*)proj_w, 2,  262144);

    mm_mma<1><<<dim3(24, 32), 256, GSM>>>(qkv_b, nullptr);
    attn_mma  <<<dim3( 8, 32), 512, ASM>>>();
    mm_mma<2><<<dim3( 8, 32), 256, GSM>>>(proj_b, out);
}

// round 12
// speedup vs baseline: 1.1838x; 1.1838x over previous
#include <cuda_runtime.h>
#include <cstdint>
#include <math.h>

#define SEQ 2048
#define MR  4096

// ---------------- scratch (device globals; no allocs) ----------------
__device__ float g_xr [MR*1024];            // x rounded to tf32
__device__ float g_wr [3*1024*1024];        // qkv_w rounded
__device__ float g_pwr[1024*1024];          // proj_w rounded
__device__ float g_qkv[(size_t)MR*3072];    // q(*0.125)|k|v rounded, row-major [s][3072]
__device__ float g_ctx[(size_t)MR*1024];    // attention out rounded

// ---------------- helpers ----------------
__device__ __forceinline__ uint32_t sm_u32(const void* p){
    uint32_t a;
    asm("{ .reg .u64 t; cvta.to.shared.u64 t, %1; cvt.u32.u64 %0, t; }" : "=r"(a) : "l"(p));
    return a;
}
__device__ __forceinline__ float rnaf(float x){
    uint32_t u; asm("cvt.rna.tf32.f32 %0, %1;" : "=r"(u) : "f"(x)); return __uint_as_float(u);
}
#define CP16(dst,src) asm volatile("cp.async.cg.shared.global [%0], [%1], 16;" :: "r"(dst),"l"(src))
#define CPC()  asm volatile("cp.async.commit_group;")
#define CPW(n) asm volatile("cp.async.wait_group %0;" :: "n"(n))

__device__ __forceinline__ void mma8(float* c, const uint32_t* a, const uint32_t* b){
    asm volatile("mma.sync.aligned.m16n8k8.row.col.f32.tf32.tf32.f32 "
        "{%0,%1,%2,%3}, {%4,%5,%6,%7}, {%8,%9}, {%0,%1,%2,%3};"
        : "+f"(c[0]),"+f"(c[1]),"+f"(c[2]),"+f"(c[3])
        : "r"(a[0]),"r"(a[1]),"r"(a[2]),"r"(a[3]), "r"(b[0]),"r"(b[1]));
}
__device__ __forceinline__ void ldsm4(uint32_t* r, uint32_t a){
    asm volatile("ldmatrix.sync.aligned.m8n8.x4.shared.b16 {%0,%1,%2,%3}, [%4];"
        : "=r"(r[0]),"=r"(r[1]),"=r"(r[2]),"=r"(r[3]) : "r"(a));
}

// ---------------------------------------------------------------------------
// fp32 -> tf32 (rna) pre-round. which: 0->g_xr, 1->g_wr, 2->g_pwr
// ---------------------------------------------------------------------------
__global__ void round_k(const float4* __restrict__ in, int which, int n4)
{
    int i = blockIdx.x * blockDim.x + threadIdx.x;
    if (i >= n4) return;
    float4* out = (which==0) ? (float4*)g_xr : (which==1) ? (float4*)g_wr : (float4*)g_pwr;
    float4 v = in[i];
    v.x = rnaf(v.x); v.y = rnaf(v.y); v.z = rnaf(v.z); v.w = rnaf(v.w);
    out[i] = v;
}

// ---------------------------------------------------------------------------
// tf32 mma.sync GEMM: C[M,N] = A[M,1024] @ B[N,1024]^T + bias
// CTA 128x128, warp tile 32x64 (4x2 warps), BK=32, 3-stage cp.async, ldmatrix.
// 256 thr, 2 CTAs/SM. dyn smem: A 3*16K | B 3*16K = 98304 B.
// MODE 1: A=g_xr, B=g_wr, N=3072 -> g_qkv (rounded; q cols scaled 0.125)
// MODE 2: A=g_ctx, B=g_pwr, N=1024 -> C (plain fp32)
// ---------------------------------------------------------------------------
template<int MODE>
__global__ __launch_bounds__(256, 2)
void mm_mma(const float* __restrict__ bias, float* __restrict__ C)
{
    extern __shared__ char smem[];
    const int N = (MODE==1) ? 3072 : 1024;
    uint32_t ab = sm_u32(smem);
    uint32_t bb = ab + 49152;
    const float* Ap = (MODE==1) ? g_xr : g_ctx;
    const float* Bp = (MODE==1) ? g_wr : g_pwr;
    float* Cp = (MODE==1) ? g_qkv : C;

    int tid = threadIdx.x, wid = tid>>5, lane = tid&31;
    int g = lane>>2, tg = lane&3;
    int wm = wid&3, wn = wid>>2;
    int bm = blockIdx.y*128, bn = blockIdx.x*128;

    // 128 rows x 32 floats (128B/row), chunk c=0..7, swizzle c ^ (r&7)
    auto aaddr = [&](int st,int r,int c){ return ab + st*16384 + r*128 + ((c ^ (r&7))<<4); };
    auto baddr = [&](int st,int r,int c){ return bb + st*16384 + r*128 + ((c ^ (r&7))<<4); };

    auto pf = [&](int kt, int st){
#pragma unroll
        for (int j=0;j<4;j++){
            int ci = j*256 + tid, r = ci>>3, c = ci&7;
            CP16(aaddr(st,r,c), Ap + (size_t)(bm+r)*1024 + kt*32 + c*4);
        }
#pragma unroll
        for (int j=0;j<4;j++){
            int ci = j*256 + tid, r = ci>>3, c = ci&7;
            CP16(baddr(st,r,c), Bp + (size_t)(bn+r)*1024 + kt*32 + c*4);
        }
    };

    float acc[2][8][4];
#pragma unroll
    for (int mt=0;mt<2;mt++)
#pragma unroll
        for (int nt=0;nt<8;nt++)
#pragma unroll
            for (int q=0;q<4;q++) acc[mt][nt][q] = 0.f;

    pf(0,0); CPC();
    pf(1,1); CPC();
    for (int kt=0; kt<32; kt++){
        int st = kt % 3;
        CPW(1);
        __syncthreads();
        if (kt+2 < 32) pf(kt+2, (kt+2)%3);
        CPC();
#pragma unroll
        for (int k8=0;k8<4;k8++){
            uint32_t a[2][4], b2[8][2];
#pragma unroll
            for (int mt=0;mt<2;mt++){
                int r = wm*32 + mt*16 + (lane&15);
                int c = k8*2 + ((lane>>4)&1);
                ldsm4(a[mt], aaddr(st,r,c));
            }
#pragma unroll
            for (int np=0;np<4;np++){
                int r = wn*64 + np*16 + (lane&7) + ((lane>>4)&1)*8;
                int c = k8*2 + ((lane>>3)&1);
                uint32_t t4[4];
                ldsm4(t4, baddr(st,r,c));
                b2[2*np][0]=t4[0];   b2[2*np][1]=t4[1];
                b2[2*np+1][0]=t4[2]; b2[2*np+1][1]=t4[3];
            }
#pragma unroll
            for (int mt=0;mt<2;mt++)
#pragma unroll
                for (int nt=0;nt<8;nt++)
                    mma8(acc[mt][nt], a[mt], b2[nt]);
        }
    }

#pragma unroll
    for (int mt=0;mt<2;mt++){
        int r0 = bm + wm*32 + mt*16 + g;
#pragma unroll
        for (int nt=0;nt<8;nt++){
            int c0 = bn + wn*64 + nt*8 + 2*tg;
            float b0 = bias[c0], b1 = bias[c0+1];
            float v0 = acc[mt][nt][0]+b0, v1 = acc[mt][nt][1]+b1;
            float v2 = acc[mt][nt][2]+b0, v3 = acc[mt][nt][3]+b1;
            if (MODE==1){
                float sc = (c0 < 1024) ? 0.125f : 1.f;
                v0=rnaf(v0*sc); v1=rnaf(v1*sc); v2=rnaf(v2*sc); v3=rnaf(v3*sc);
            }
            *(float2*)&Cp[(size_t)r0*N + c0]     = make_float2(v0,v1);
            *(float2*)&Cp[(size_t)(r0+8)*N + c0] = make_float2(v2,v3);
        }
    }
}

// ---------------------------------------------------------------------------
// Flash attention (R10 config): CTA = 256 queries of one (b,h), 256 thr,
// 8 warps x 32 rows (warp tile 32x64). Bc=64 keys/iter, 32 iters.
// dyn smem: Q[256x64f swz] 65536 | K 2x16384 | V 2x(64x272B) | P 65536 = 198656
// ---------------------------------------------------------------------------
__global__ __launch_bounds__(256, 1)
void attn_mma()
{
    extern __shared__ char smem[];
    uint32_t sb = sm_u32(smem);
    const uint32_t QO = 0, KO = 65536, VO = 98304, PO = 133120;

    int tid = threadIdx.x, wid = tid>>5, lane = tid&31;
    int g = lane>>2, tg = lane&3;
    int bh = blockIdx.y, b = bh>>4, hh = bh&15;
    int q0 = blockIdx.x * 256;

    const float* Qg  = g_qkv + (size_t)(b*2048 + q0)*3072 + hh*64;
    const float* KVg = g_qkv + (size_t)(b*2048)*3072 + 1024 + hh*64;

    auto qaddr = [&](int r,int c){ return sb + QO + r*256 + ((c ^ (r&7))<<4); };
    auto kaddr = [&](int st,int r,int c){ return sb + KO + st*16384 + r*256 + ((c ^ (r&7))<<4); };
    auto vaddr = [&](int st,int r,int c){ return sb + VO + st*17408 + r*272 + c*16; };
    auto paddr = [&](int r,int c){ return sb + PO + r*256 + ((c ^ (r&7))<<4); };

#pragma unroll
    for (int j=0;j<16;j++){
        int ci = j*256 + tid, r = ci>>4, c = ci&15;
        CP16(qaddr(r,c), Qg + (size_t)r*3072 + c*4);
    }
    auto pf = [&](int it, int st){
        int kt = it * 64;
#pragma unroll
        for (int j=0;j<4;j++){
            int ci = j*256 + tid, r = ci>>4, c = ci&15;
            CP16(kaddr(st,r,c), KVg + (size_t)(kt+r)*3072 + c*4);
        }
#pragma unroll
        for (int j=0;j<4;j++){
            int ci = j*256 + tid, r = ci>>4, c = ci&15;
            CP16(vaddr(st,r,c), KVg + (size_t)(kt+r)*3072 + 1024 + c*4);
        }
    };

    float o[2][8][4], m[2][2], l[2][2];
#pragma unroll
    for (int mt=0;mt<2;mt++){
        m[mt][0]=m[mt][1]=-1e30f; l[mt][0]=l[mt][1]=0.f;
#pragma unroll
        for (int nt=0;nt<8;nt++)
#pragma unroll
            for (int q=0;q<4;q++) o[mt][nt][q]=0.f;
    }

    pf(0,0); CPC();
    for (int it=0; it<32; it++){
        int st = it & 1;
        if (it+1 < 32){ pf(it+1, st^1); CPC(); CPW(1); } else CPW(0);
        __syncthreads();

        // ---- S = Q @ K^T : warp rows wid*32..+31, cols 0..63 ----
        float s[2][8][4];
#pragma unroll
        for (int mt=0;mt<2;mt++)
#pragma unroll
            for (int nt=0;nt<8;nt++)
#pragma unroll
                for (int q=0;q<4;q++) s[mt][nt][q]=0.f;
#pragma unroll
        for (int k8=0;k8<8;k8++){
            uint32_t a[2][4], b2[8][2];
#pragma unroll
            for (int mt=0;mt<2;mt++){
                int r = wid*32 + mt*16 + (lane&15);
                int c = k8*2 + ((lane>>4)&1);
                ldsm4(a[mt], qaddr(r,c));
            }
#pragma unroll
            for (int np=0;np<4;np++){
                int r = np*16 + (lane&7) + ((lane>>4)&1)*8;
                int c = k8*2 + ((lane>>3)&1);
                uint32_t t4[4];
                ldsm4(t4, kaddr(st,r,c));
                b2[2*np][0]=t4[0];   b2[2*np][1]=t4[1];
                b2[2*np+1][0]=t4[2]; b2[2*np+1][1]=t4[3];
            }
#pragma unroll
            for (int mt=0;mt<2;mt++)
#pragma unroll
                for (int nt=0;nt<8;nt++)
                    mma8(s[mt][nt], a[mt], b2[nt]);
        }

        // ---- online softmax: 4 row-states per thread (mt x half) ----
        float al[2][2];
#pragma unroll
        for (int mt=0;mt<2;mt++)
#pragma unroll
            for (int hf=0;hf<2;hf++){
                float mx = -1e30f;
#pragma unroll
                for (int nt=0;nt<8;nt++)
                    mx = fmaxf(mx, fmaxf(s[mt][nt][2*hf], s[mt][nt][2*hf+1]));
                mx = fmaxf(mx, __shfl_xor_sync(0xffffffffu, mx, 1));
                mx = fmaxf(mx, __shfl_xor_sync(0xffffffffu, mx, 2));
                float mn = fmaxf(m[mt][hf], mx);
                al[mt][hf] = __expf(m[mt][hf] - mn);
                m[mt][hf] = mn;
                float sum = 0.f;
#pragma unroll
                for (int nt=0;nt<8;nt++){
                    s[mt][nt][2*hf]   = __expf(s[mt][nt][2*hf]   - mn); sum += s[mt][nt][2*hf];
                    s[mt][nt][2*hf+1] = __expf(s[mt][nt][2*hf+1] - mn); sum += s[mt][nt][2*hf+1];
                }
                sum += __shfl_xor_sync(0xffffffffu, sum, 1);
                sum += __shfl_xor_sync(0xffffffffu, sum, 2);
                l[mt][hf] = l[mt][hf]*al[mt][hf] + sum;
            }
#pragma unroll
        for (int mt=0;mt<2;mt++)
#pragma unroll
            for (int nt=0;nt<8;nt++){
                o[mt][nt][0]*=al[mt][0]; o[mt][nt][1]*=al[mt][0];
                o[mt][nt][2]*=al[mt][1]; o[mt][nt][3]*=al[mt][1];
            }

        // ---- stage P (rounded) via GENERIC pointers, own-warp rows ----
#pragma unroll
        for (int mt=0;mt<2;mt++){
            int row = wid*32 + mt*16 + g;
            int coff = (2*tg & 3) * 4;
#pragma unroll
            for (int nt=0;nt<8;nt++){
                int ch = (nt*8 + 2*tg) >> 2;
                char* p0 = smem + PO + row*256     + (((ch ^ (row&7))<<4))     + coff;
                char* p1 = smem + PO + (row+8)*256 + (((ch ^ ((row+8)&7))<<4)) + coff;
                *(float2*)p0 = make_float2(rnaf(s[mt][nt][0]), rnaf(s[mt][nt][1]));
                *(float2*)p1 = make_float2(rnaf(s[mt][nt][2]), rnaf(s[mt][nt][3]));
            }
        }
        __syncwarp();

        // ---- O += P @ V ----
#pragma unroll
        for (int k8=0;k8<8;k8++){
            uint32_t a[2][4];
#pragma unroll
            for (int mt=0;mt<2;mt++){
                int r = wid*32 + mt*16 + (lane&15);
                int c = k8*2 + ((lane>>4)&1);
                ldsm4(a[mt], paddr(r,c));
            }
            const float* v0 = (const float*)(smem + VO + st*17408 + (k8*8+tg  )*272);
            const float* v1 = (const float*)(smem + VO + st*17408 + (k8*8+tg+4)*272);
#pragma unroll
            for (int nt=0;nt<8;nt++){
                uint32_t b2[2] = { __float_as_uint(v0[nt*8+g]), __float_as_uint(v1[nt*8+g]) };
                mma8(o[0][nt], a[0], b2);
                mma8(o[1][nt], a[1], b2);
            }
        }
        __syncthreads();
    }

    // ---- epilogue: normalize, round, write ctx ----
#pragma unroll
    for (int mt=0;mt<2;mt++){
        float i0 = 1.f/l[mt][0], i1 = 1.f/l[mt][1];
        int r0 = q0 + wid*32 + mt*16 + g;
        float* Cg = g_ctx + (size_t)(b*2048 + r0)*1024 + hh*64;
#pragma unroll
        for (int nt=0;nt<8;nt++){
            int c = nt*8 + 2*tg;
            *(float2*)&Cg[c]          = make_float2(rnaf(o[mt][nt][0]*i0), rnaf(o[mt][nt][1]*i0));
            *(float2*)&Cg[8*1024 + c] = make_float2(rnaf(o[mt][nt][2]*i1), rnaf(o[mt][nt][3]*i1));
        }
    }
}

// ---------------------------------------------------------------------------
extern "C" void kernel_launch(void* const* d_in, const int* in_sizes, int n_in,
                              void* d_out, int out_size)
{
    const float* x      = (const float*)d_in[0];
    const float* qkv_w  = (const float*)d_in[1];
    const float* qkv_b  = (const float*)d_in[2];
    const float* proj_w = (const float*)d_in[3];
    const float* proj_b = (const float*)d_in[4];
    float* out = (float*)d_out;
    (void)in_sizes; (void)n_in; (void)out_size;

    const int GSM = 98304;    // GEMM: 3-stage A(16K)+B(16K)
    const int ASM = 198656;   // attention
    cudaFuncSetAttribute(mm_mma<1>, cudaFuncAttributeMaxDynamicSharedMemorySize, GSM);
    cudaFuncSetAttribute(mm_mma<2>, cudaFuncAttributeMaxDynamicSharedMemorySize, GSM);
    cudaFuncSetAttribute(attn_mma,  cudaFuncAttributeMaxDynamicSharedMemorySize, ASM);

    round_k<<<4096, 256>>>((const float4*)x,      0, 1048576);
    round_k<<<3072, 256>>>((const float4*)qkv_w,  1,  786432);
    round_k<<<1024, 256>>>((const float4*)proj_w, 2,  262144);

    mm_mma<1><<<dim3(24, 32), 256, GSM>>>(qkv_b, nullptr);
    attn_mma  <<<dim3( 8, 32), 256, ASM>>>();
    mm_mma<2><<<dim3( 8, 32), 256, GSM>>>(proj_b, out);
}